// round 11
// baseline (speedup 1.0000x reference)
#include <cuda_runtime.h>
#include <math.h>

// ---------------------------------------------------------------------------
// AccFlow2FrameEncoder: dynamic pillar feature net on 2 clouds, grid diff.
//
// Pipeline (all graph-capturable, scratch in __device__ globals):
//   1. k_zero     : zero per-segment counts (4 * 262144 segments)
//   2. k_count    : atomic count points per (cloud,batch,voxel)
//   3. k_scan1/2/3: exclusive scan of the 1,048,576 counts -> segment starts
//   4. k_scatter  : counting-sort point xyz into segment order
//   5. k_voxel    : one warp per output voxel: gather points of both clouds,
//                   cluster mean -> 9-feat -> Linear(9,64)+BN+ReLU -> mean,
//                   write diff (pc1 - pc0) as coalesced float2 per lane.
// ---------------------------------------------------------------------------

#define GXD 512
#define GYD 512
#define NVOX (GXD * GYD)          // 262144
#define NSEG (4 * NVOX)           // 1048576 = 1024 * 1024
#define CAP  1048576              // sorted-point capacity (>= 400000)

__device__ int    g_cnt[NSEG];
__device__ int    g_start[NSEG + 1];
__device__ int    g_cursor[NSEG];
__device__ int    g_bsum[1024];
__device__ int    g_boff[1024];
__device__ float4 g_sorted[CAP];

// Voxel id, bitwise-matching the JAX reference:
//   ix = clip(int(floor((x - X_MIN) / VX)), 0, 511)   (IEEE f32 sub + div)
__device__ __forceinline__ int voxel_id(float x, float y) {
    int ix = (int)floorf(__fdiv_rn(x + 51.2f, 0.2f));
    int iy = (int)floorf(__fdiv_rn(y + 51.2f, 0.2f));
    ix = min(max(ix, 0), GXD - 1);
    iy = min(max(iy, 0), GYD - 1);
    return ix * GYD + iy;
}

__global__ void k_zero() {
    int i = blockIdx.x * blockDim.x + threadIdx.x;
    if (i < NSEG) g_cnt[i] = 0;
}

// t in [0, 2P): first P points are pc0 (batches 0..B-1), next P are pc1.
// segment index = g * NVOX + vid, with g = (cloud ? 2 : 0) + batch.
__global__ void k_count(const float* __restrict__ pc0,
                        const float* __restrict__ pc1, int P, int N) {
    int t = blockIdx.x * blockDim.x + threadIdx.x;
    if (t >= 2 * P) return;
    const float* pc = (t < P) ? pc0 : pc1;
    int r = (t < P) ? t : t - P;
    float x = pc[3 * r + 0];
    float y = pc[3 * r + 1];
    int b = r / N;
    int g = ((t < P) ? 0 : 2) + b;
    atomicAdd(&g_cnt[g * NVOX + voxel_id(x, y)], 1);
}

// Block-level inclusive scan (Hillis-Steele) over 1024 elements.
__device__ __forceinline__ int block_scan_inclusive(int x, int* sh) {
    int t = threadIdx.x;
    sh[t] = x;
    __syncthreads();
#pragma unroll
    for (int off = 1; off < 1024; off <<= 1) {
        int v = (t >= off) ? sh[t - off] : 0;
        __syncthreads();
        sh[t] += v;
        __syncthreads();
    }
    return sh[t];
}

__global__ void k_scan1() {  // <<<1024, 1024>>>
    __shared__ int sh[1024];
    int i = blockIdx.x * 1024 + threadIdx.x;
    int x = g_cnt[i];
    int incl = block_scan_inclusive(x, sh);
    g_start[i] = incl - x;  // exclusive within block
    if (threadIdx.x == 1023) g_bsum[blockIdx.x] = incl;
}

__global__ void k_scan2() {  // <<<1, 1024>>>
    __shared__ int sh[1024];
    int x = g_bsum[threadIdx.x];
    int incl = block_scan_inclusive(x, sh);
    g_boff[threadIdx.x] = incl - x;
    if (threadIdx.x == 1023) g_start[NSEG] = incl;  // sentinel = total points
}

__global__ void k_scan3() {  // <<<1024, 1024>>>
    int i = blockIdx.x * 1024 + threadIdx.x;
    int v = g_start[i] + g_boff[blockIdx.x];
    g_start[i] = v;
    g_cursor[i] = v;
}

__global__ void k_scatter(const float* __restrict__ pc0,
                          const float* __restrict__ pc1, int P, int N) {
    int t = blockIdx.x * blockDim.x + threadIdx.x;
    if (t >= 2 * P) return;
    const float* pc = (t < P) ? pc0 : pc1;
    int r = (t < P) ? t : t - P;
    float x = pc[3 * r + 0];
    float y = pc[3 * r + 1];
    float z = pc[3 * r + 2];
    int b = r / N;
    int g = ((t < P) ? 0 : 2) + b;
    int idx = g * NVOX + voxel_id(x, y);
    int slot = atomicAdd(&g_cursor[idx], 1);
    if (slot < CAP) g_sorted[slot] = make_float4(x, y, z, 0.f);
}

// Gather one cloud's segment [s,e): cluster mean, then per-point
// Linear(9->2 channels of this lane)+BN+ReLU, then segment mean.
// All lanes execute identically (uniform loads, broadcast in L1).
__device__ __forceinline__ float2 accum_cloud(int s, int e, float cx, float cy,
                                              const float2* w,
                                              float s0, float s1,
                                              float t0, float t1) {
    float2 r;
    r.x = 0.f;
    r.y = 0.f;
    int n = e - s;
    if (n <= 0) return r;

    float sx = 0.f, sy = 0.f, sz = 0.f;
    for (int i = s; i < e; i++) {
        float4 p = g_sorted[i];
        sx += p.x;
        sy += p.y;
        sz += p.z;
    }
    float fn = (float)n;
    float cmx = sx / fn, cmy = sy / fn, cmz = sz / fn;

    float a0 = 0.f, a1 = 0.f;
    for (int i = s; i < e; i++) {
        float4 p = g_sorted[i];
        float f3 = p.x - cmx, f4 = p.y - cmy, f5 = p.z - cmz;
        float f6 = p.x - cx, f7 = p.y - cy;  // f8 = p.z - 0
        float h0 = p.x * w[0].x + p.y * w[1].x + p.z * w[2].x
                 + f3 * w[3].x + f4 * w[4].x + f5 * w[5].x
                 + f6 * w[6].x + f7 * w[7].x + p.z * w[8].x;
        float h1 = p.x * w[0].y + p.y * w[1].y + p.z * w[2].y
                 + f3 * w[3].y + f4 * w[4].y + f5 * w[5].y
                 + f6 * w[6].y + f7 * w[7].y + p.z * w[8].y;
        a0 += fmaxf(h0 * s0 + t0, 0.f);
        a1 += fmaxf(h1 * s1 + t1, 0.f);
    }
    r.x = a0 / fn;
    r.y = a1 / fn;
    return r;
}

// One warp handles 32 consecutive output voxels (same batch: NVOX % 32 == 0).
// Lane owns channels (2*lane, 2*lane+1); per voxel writes one float2 ->
// a single coalesced 256B STG per warp per voxel.
__global__ void k_voxel(const float* __restrict__ W,
                        const float* __restrict__ gamma,
                        const float* __restrict__ beta,
                        const float* __restrict__ mean,
                        const float* __restrict__ var,
                        float2* __restrict__ out) {
    const int lane = threadIdx.x & 31;
    const int warp = (blockIdx.x * blockDim.x + threadIdx.x) >> 5;
    const int nwarps = (gridDim.x * blockDim.x) >> 5;
    const int c0 = 2 * lane;

    // Weight columns + folded BN params for this lane's 2 channels.
    float2 w[9];
#pragma unroll
    for (int k = 0; k < 9; k++)
        w[k] = *reinterpret_cast<const float2*>(W + 64 * k + c0);
    float2 G = *reinterpret_cast<const float2*>(gamma + c0);
    float2 Bt = *reinterpret_cast<const float2*>(beta + c0);
    float2 M = *reinterpret_cast<const float2*>(mean + c0);
    float2 V = *reinterpret_cast<const float2*>(var + c0);
    float s0 = G.x / sqrtf(V.x + 1e-3f);
    float s1 = G.y / sqrtf(V.y + 1e-3f);
    float t0 = Bt.x - M.x * s0;
    float t1 = Bt.y - M.y * s1;

    const int nchunks = (2 * NVOX) / 32;  // 16384 chunks of 32 voxels
    for (int ch = warp; ch < nchunks; ch += nwarps) {
        int vbase = ch * 32;  // global voxel index b*NVOX + v
        // Coalesced segment-offset loads for 32 voxels, both clouds.
        int sA = g_start[vbase + lane];
        int eA = g_start[vbase + lane + 1];
        int sB = g_start[vbase + 2 * NVOX + lane];
        int eB = g_start[vbase + 2 * NVOX + lane + 1];

#pragma unroll 1
        for (int k = 0; k < 32; k++) {
            int s0v = __shfl_sync(0xffffffffu, sA, k);
            int e0v = __shfl_sync(0xffffffffu, eA, k);
            int s1v = __shfl_sync(0xffffffffu, sB, k);
            int e1v = __shfl_sync(0xffffffffu, eB, k);

            float2 r;
            if ((e0v == s0v) && (e1v == s1v)) {
                r.x = 0.f;
                r.y = 0.f;
            } else {
                int v = (vbase + k) & (NVOX - 1);  // voxel within batch
                float cx = ((float)(v >> 9) + 0.5f) * 0.2f + (-51.2f);
                float cy = ((float)(v & 511) + 0.5f) * 0.2f + (-51.2f);
                float2 m1 = accum_cloud(s1v, e1v, cx, cy, w, s0, s1, t0, t1);
                float2 m0 = accum_cloud(s0v, e0v, cx, cy, w, s0, s1, t0, t1);
                r.x = m1.x - m0.x;
                r.y = m1.y - m0.y;
            }
            out[(size_t)(vbase + k) * 32 + lane] = r;
        }
    }
}

extern "C" void kernel_launch(void* const* d_in, const int* in_sizes, int n_in,
                              void* d_out, int out_size) {
    const float* pc0   = (const float*)d_in[0];
    const float* pc1   = (const float*)d_in[1];
    const float* W     = (const float*)d_in[2];
    const float* gamma = (const float*)d_in[3];
    const float* beta  = (const float*)d_in[4];
    const float* mean  = (const float*)d_in[5];
    const float* var   = (const float*)d_in[6];

    int P = in_sizes[0] / 3;  // B*N points per cloud (200000)
    int N = P / 2;            // points per batch   (100000)

    k_zero<<<NSEG / 1024, 1024>>>();

    int pts_blocks = (2 * P + 255) / 256;
    k_count<<<pts_blocks, 256>>>(pc0, pc1, P, N);

    k_scan1<<<1024, 1024>>>();
    k_scan2<<<1, 1024>>>();
    k_scan3<<<1024, 1024>>>();

    k_scatter<<<pts_blocks, 256>>>(pc0, pc1, P, N);

    k_voxel<<<2048, 256>>>(W, gamma, beta, mean, var, (float2*)d_out);
}

// round 12
// speedup vs baseline: 1.0004x; 1.0004x over previous
#include <cuda_runtime.h>
#include <math.h>

// ---------------------------------------------------------------------------
// AccFlow2FrameEncoder: dynamic pillar feature net on 2 clouds, grid diff.
//
// Pipeline (all graph-capturable, scratch in __device__ globals):
//   1. k_zero     : zero per-segment counts (4 * 262144 segments)
//   2. k_count    : atomic count points per (cloud,batch,voxel)
//   3. k_scan1/2/3: exclusive scan of the 1,048,576 counts -> segment starts
//   4. k_scatter  : counting-sort point xyz into segment order
//   5. k_voxel    : one warp per output voxel: gather points of both clouds,
//                   cluster mean -> 9-feat -> Linear(9,64)+BN+ReLU -> mean,
//                   write diff (pc1 - pc0) as coalesced float2 per lane.
// ---------------------------------------------------------------------------

#define GXD 512
#define GYD 512
#define NVOX (GXD * GYD)          // 262144
#define NSEG (4 * NVOX)           // 1048576 = 1024 * 1024
#define CAP  1048576              // sorted-point capacity (>= 400000)

__device__ int    g_cnt[NSEG];
__device__ int    g_start[NSEG + 1];
__device__ int    g_cursor[NSEG];
__device__ int    g_bsum[1024];
__device__ int    g_boff[1024];
__device__ float4 g_sorted[CAP];

// Voxel id, bitwise-matching the JAX reference:
//   ix = clip(int(floor((x - X_MIN) / VX)), 0, 511)   (IEEE f32 sub + div)
__device__ __forceinline__ int voxel_id(float x, float y) {
    int ix = (int)floorf(__fdiv_rn(x + 51.2f, 0.2f));
    int iy = (int)floorf(__fdiv_rn(y + 51.2f, 0.2f));
    ix = min(max(ix, 0), GXD - 1);
    iy = min(max(iy, 0), GYD - 1);
    return ix * GYD + iy;
}

__global__ void k_zero() {
    int i = blockIdx.x * blockDim.x + threadIdx.x;
    if (i < NSEG) g_cnt[i] = 0;
}

// t in [0, 2P): first P points are pc0 (batches 0..B-1), next P are pc1.
// segment index = g * NVOX + vid, with g = (cloud ? 2 : 0) + batch.
__global__ void k_count(const float* __restrict__ pc0,
                        const float* __restrict__ pc1, int P, int N) {
    int t = blockIdx.x * blockDim.x + threadIdx.x;
    if (t >= 2 * P) return;
    const float* pc = (t < P) ? pc0 : pc1;
    int r = (t < P) ? t : t - P;
    float x = pc[3 * r + 0];
    float y = pc[3 * r + 1];
    int b = r / N;
    int g = ((t < P) ? 0 : 2) + b;
    atomicAdd(&g_cnt[g * NVOX + voxel_id(x, y)], 1);
}

// Block-level inclusive scan (Hillis-Steele) over 1024 elements.
__device__ __forceinline__ int block_scan_inclusive(int x, int* sh) {
    int t = threadIdx.x;
    sh[t] = x;
    __syncthreads();
#pragma unroll
    for (int off = 1; off < 1024; off <<= 1) {
        int v = (t >= off) ? sh[t - off] : 0;
        __syncthreads();
        sh[t] += v;
        __syncthreads();
    }
    return sh[t];
}

__global__ void k_scan1() {  // <<<1024, 1024>>>
    __shared__ int sh[1024];
    int i = blockIdx.x * 1024 + threadIdx.x;
    int x = g_cnt[i];
    int incl = block_scan_inclusive(x, sh);
    g_start[i] = incl - x;  // exclusive within block
    if (threadIdx.x == 1023) g_bsum[blockIdx.x] = incl;
}

__global__ void k_scan2() {  // <<<1, 1024>>>
    __shared__ int sh[1024];
    int x = g_bsum[threadIdx.x];
    int incl = block_scan_inclusive(x, sh);
    g_boff[threadIdx.x] = incl - x;
    if (threadIdx.x == 1023) g_start[NSEG] = incl;  // sentinel = total points
}

__global__ void k_scan3() {  // <<<1024, 1024>>>
    int i = blockIdx.x * 1024 + threadIdx.x;
    int v = g_start[i] + g_boff[blockIdx.x];
    g_start[i] = v;
    g_cursor[i] = v;
}

__global__ void k_scatter(const float* __restrict__ pc0,
                          const float* __restrict__ pc1, int P, int N) {
    int t = blockIdx.x * blockDim.x + threadIdx.x;
    if (t >= 2 * P) return;
    const float* pc = (t < P) ? pc0 : pc1;
    int r = (t < P) ? t : t - P;
    float x = pc[3 * r + 0];
    float y = pc[3 * r + 1];
    float z = pc[3 * r + 2];
    int b = r / N;
    int g = ((t < P) ? 0 : 2) + b;
    int idx = g * NVOX + voxel_id(x, y);
    int slot = atomicAdd(&g_cursor[idx], 1);
    if (slot < CAP) g_sorted[slot] = make_float4(x, y, z, 0.f);
}

// Gather one cloud's segment [s,e): cluster mean, then per-point
// Linear(9->2 channels of this lane)+BN+ReLU, then segment mean.
// All lanes execute identically (uniform loads, broadcast in L1).
__device__ __forceinline__ float2 accum_cloud(int s, int e, float cx, float cy,
                                              const float2* w,
                                              float s0, float s1,
                                              float t0, float t1) {
    float2 r;
    r.x = 0.f;
    r.y = 0.f;
    int n = e - s;
    if (n <= 0) return r;

    float sx = 0.f, sy = 0.f, sz = 0.f;
    for (int i = s; i < e; i++) {
        float4 p = g_sorted[i];
        sx += p.x;
        sy += p.y;
        sz += p.z;
    }
    float fn = (float)n;
    float cmx = sx / fn, cmy = sy / fn, cmz = sz / fn;

    float a0 = 0.f, a1 = 0.f;
    for (int i = s; i < e; i++) {
        float4 p = g_sorted[i];
        float f3 = p.x - cmx, f4 = p.y - cmy, f5 = p.z - cmz;
        float f6 = p.x - cx, f7 = p.y - cy;  // f8 = p.z - 0
        float h0 = p.x * w[0].x + p.y * w[1].x + p.z * w[2].x
                 + f3 * w[3].x + f4 * w[4].x + f5 * w[5].x
                 + f6 * w[6].x + f7 * w[7].x + p.z * w[8].x;
        float h1 = p.x * w[0].y + p.y * w[1].y + p.z * w[2].y
                 + f3 * w[3].y + f4 * w[4].y + f5 * w[5].y
                 + f6 * w[6].y + f7 * w[7].y + p.z * w[8].y;
        a0 += fmaxf(h0 * s0 + t0, 0.f);
        a1 += fmaxf(h1 * s1 + t1, 0.f);
    }
    r.x = a0 / fn;
    r.y = a1 / fn;
    return r;
}

// One warp handles 32 consecutive output voxels (same batch: NVOX % 32 == 0).
// Lane owns channels (2*lane, 2*lane+1); per voxel writes one float2 ->
// a single coalesced 256B STG per warp per voxel.
__global__ void k_voxel(const float* __restrict__ W,
                        const float* __restrict__ gamma,
                        const float* __restrict__ beta,
                        const float* __restrict__ mean,
                        const float* __restrict__ var,
                        float2* __restrict__ out) {
    const int lane = threadIdx.x & 31;
    const int warp = (blockIdx.x * blockDim.x + threadIdx.x) >> 5;
    const int nwarps = (gridDim.x * blockDim.x) >> 5;
    const int c0 = 2 * lane;

    // Weight columns + folded BN params for this lane's 2 channels.
    float2 w[9];
#pragma unroll
    for (int k = 0; k < 9; k++)
        w[k] = *reinterpret_cast<const float2*>(W + 64 * k + c0);
    float2 G = *reinterpret_cast<const float2*>(gamma + c0);
    float2 Bt = *reinterpret_cast<const float2*>(beta + c0);
    float2 M = *reinterpret_cast<const float2*>(mean + c0);
    float2 V = *reinterpret_cast<const float2*>(var + c0);
    float s0 = G.x / sqrtf(V.x + 1e-3f);
    float s1 = G.y / sqrtf(V.y + 1e-3f);
    float t0 = Bt.x - M.x * s0;
    float t1 = Bt.y - M.y * s1;

    const int nchunks = (2 * NVOX) / 32;  // 16384 chunks of 32 voxels
    for (int ch = warp; ch < nchunks; ch += nwarps) {
        int vbase = ch * 32;  // global voxel index b*NVOX + v
        // Coalesced segment-offset loads for 32 voxels, both clouds.
        int sA = g_start[vbase + lane];
        int eA = g_start[vbase + lane + 1];
        int sB = g_start[vbase + 2 * NVOX + lane];
        int eB = g_start[vbase + 2 * NVOX + lane + 1];

#pragma unroll 1
        for (int k = 0; k < 32; k++) {
            int s0v = __shfl_sync(0xffffffffu, sA, k);
            int e0v = __shfl_sync(0xffffffffu, eA, k);
            int s1v = __shfl_sync(0xffffffffu, sB, k);
            int e1v = __shfl_sync(0xffffffffu, eB, k);

            float2 r;
            if ((e0v == s0v) && (e1v == s1v)) {
                r.x = 0.f;
                r.y = 0.f;
            } else {
                int v = (vbase + k) & (NVOX - 1);  // voxel within batch
                float cx = ((float)(v >> 9) + 0.5f) * 0.2f + (-51.2f);
                float cy = ((float)(v & 511) + 0.5f) * 0.2f + (-51.2f);
                float2 m1 = accum_cloud(s1v, e1v, cx, cy, w, s0, s1, t0, t1);
                float2 m0 = accum_cloud(s0v, e0v, cx, cy, w, s0, s1, t0, t1);
                r.x = m1.x - m0.x;
                r.y = m1.y - m0.y;
            }
            out[(size_t)(vbase + k) * 32 + lane] = r;
        }
    }
}

extern "C" void kernel_launch(void* const* d_in, const int* in_sizes, int n_in,
                              void* d_out, int out_size) {
    const float* pc0   = (const float*)d_in[0];
    const float* pc1   = (const float*)d_in[1];
    const float* W     = (const float*)d_in[2];
    const float* gamma = (const float*)d_in[3];
    const float* beta  = (const float*)d_in[4];
    const float* mean  = (const float*)d_in[5];
    const float* var   = (const float*)d_in[6];

    int P = in_sizes[0] / 3;  // B*N points per cloud (200000)
    int N = P / 2;            // points per batch   (100000)

    k_zero<<<NSEG / 1024, 1024>>>();

    int pts_blocks = (2 * P + 255) / 256;
    k_count<<<pts_blocks, 256>>>(pc0, pc1, P, N);

    k_scan1<<<1024, 1024>>>();
    k_scan2<<<1, 1024>>>();
    k_scan3<<<1024, 1024>>>();

    k_scatter<<<pts_blocks, 256>>>(pc0, pc1, P, N);

    k_voxel<<<2048, 256>>>(W, gamma, beta, mean, var, (float2*)d_out);
}